// round 9
// baseline (speedup 1.0000x reference)
#include <cuda_runtime.h>
#include <cuda_bf16.h>
#include <math.h>
#include <stdint.h>

constexpr int NB = 32;      // batch
constexpr int NC = 512;     // channels
constexpr int NL = 512;     // length
constexpr int NG = 32;      // groups
constexpr float GEPS = 1e-5f;

// Scratch (static device globals: allocation-free, graph-safe) — bf16
__device__ __nv_bfloat16 g_xnT[NB * NL * NC];     // GN(x), TRANSPOSED [l][c]
__device__ __nv_bfloat16 g_cn [NB * NC * NC];     // GN(ctx), natural [c][l]
__device__ __nv_bfloat16 g_q  [NB * NL * NC];     // qT [l][o], pre-scaled by 1/8
__device__ __nv_bfloat16 g_kv [NB * NC * 2 * NC]; // kv [c][o]
__device__ __nv_bfloat16 g_aT [NB * NL * NC];     // attn out, TRANSPOSED [l][c]
__device__ __nv_bfloat16 g_qw [NC * NC];          // bf16 weights
__device__ __nv_bfloat16 g_kvw[2 * NC * NC];
__device__ __nv_bfloat16 g_pw [NC * NC];

// ===========================================================================
// PTX helpers (plain sm_100-compatible)
// ===========================================================================
__device__ __forceinline__ uint32_t smem_u32(const void* p) {
    uint32_t a;
    asm("{ .reg .u64 t; cvta.to.shared.u64 t, %1; cvt.u32.u64 %0, t; }"
        : "=r"(a) : "l"(p));
    return a;
}
__device__ __forceinline__ void cp_async16(uint32_t dst, const void* src) {
    asm volatile("{ .reg .u64 g; cvta.to.global.u64 g, %1; "
                 "cp.async.cg.shared.global [%0], [g], 16; }"
                 :: "r"(dst), "l"(src) : "memory");
}
__device__ __forceinline__ void cp_commit() {
    asm volatile("cp.async.commit_group;" ::: "memory");
}
__device__ __forceinline__ void cp_wait1() {
    asm volatile("cp.async.wait_group 1;" ::: "memory");
}
__device__ __forceinline__ void cp_wait0() {
    asm volatile("cp.async.wait_group 0;" ::: "memory");
}
__device__ __forceinline__ void ldsm4(uint32_t* r, uint32_t a) {
    asm volatile("ldmatrix.sync.aligned.m8n8.x4.shared.b16 {%0,%1,%2,%3}, [%4];"
                 : "=r"(r[0]), "=r"(r[1]), "=r"(r[2]), "=r"(r[3]) : "r"(a));
}
__device__ __forceinline__ void ldsm4t(uint32_t* r, uint32_t a) {
    asm volatile("ldmatrix.sync.aligned.m8n8.x4.trans.shared.b16 {%0,%1,%2,%3}, [%4];"
                 : "=r"(r[0]), "=r"(r[1]), "=r"(r[2]), "=r"(r[3]) : "r"(a));
}
__device__ __forceinline__ void mma_bf16(float* c, const uint32_t* a, const uint32_t* b) {
    asm volatile(
        "mma.sync.aligned.m16n8k16.row.col.f32.bf16.bf16.f32 "
        "{%0,%1,%2,%3}, {%4,%5,%6,%7}, {%8,%9}, {%0,%1,%2,%3};"
        : "+f"(c[0]), "+f"(c[1]), "+f"(c[2]), "+f"(c[3])
        : "r"(a[0]), "r"(a[1]), "r"(a[2]), "r"(a[3]), "r"(b[0]), "r"(b[1]));
}
__device__ __forceinline__ uint32_t packbf(float lo, float hi) {
    __nv_bfloat162 h = __floats2bfloat162_rn(lo, hi);
    return *reinterpret_cast<uint32_t*>(&h);
}
__device__ __forceinline__ float qmax(float v) {
    v = fmaxf(v, __shfl_xor_sync(0xffffffffu, v, 1));
    v = fmaxf(v, __shfl_xor_sync(0xffffffffu, v, 2));
    return v;
}
__device__ __forceinline__ float qsum(float v) {
    v += __shfl_xor_sync(0xffffffffu, v, 1);
    v += __shfl_xor_sync(0xffffffffu, v, 2);
    return v;
}

// ===========================================================================
// fp32 -> bf16 weight conversion
// ===========================================================================
__global__ __launch_bounds__(256) void cvt_bf16_kernel(
    const float* __restrict__ s, __nv_bfloat16* __restrict__ d, int n4)
{
    const int i = blockIdx.x * 256 + threadIdx.x;
    if (i >= n4) return;
    const float4 v = reinterpret_cast<const float4*>(s)[i];
    uint2 u;
    u.x = packbf(v.x, v.y);
    u.y = packbf(v.z, v.w);
    reinterpret_cast<uint2*>(d)[i] = u;
}

// ===========================================================================
// GroupNorm: one block per (batch, group). bf16 output.
// TRANS=true writes out[l][c] layout (for xnT).
// ===========================================================================
template<bool TRANS>
__global__ __launch_bounds__(256) void groupnorm_kernel(
    const float* __restrict__ in, const float* __restrict__ w,
    const float* __restrict__ bia, __nv_bfloat16* __restrict__ out)
{
    const int bg = blockIdx.x;
    const int g = bg % NG;
    const float4* src = reinterpret_cast<const float4*>(in) + (size_t)bg * 2048;
    const int tid = threadIdx.x;

    float s = 0.f, ss = 0.f;
    float4 v[8];
#pragma unroll
    for (int i = 0; i < 8; i++) {
        v[i] = src[tid + i * 256];
        s  += v[i].x + v[i].y + v[i].z + v[i].w;
        ss += v[i].x * v[i].x + v[i].y * v[i].y + v[i].z * v[i].z + v[i].w * v[i].w;
    }
    __shared__ float red[2][8];
#pragma unroll
    for (int o = 16; o > 0; o >>= 1) {
        s  += __shfl_xor_sync(0xffffffffu, s, o);
        ss += __shfl_xor_sync(0xffffffffu, ss, o);
    }
    const int warp = tid >> 5, lane = tid & 31;
    if (lane == 0) { red[0][warp] = s; red[1][warp] = ss; }
    __syncthreads();
    if (warp == 0) {
        s = red[0][lane & 7]; ss = red[1][lane & 7];
#pragma unroll
        for (int o = 4; o > 0; o >>= 1) {
            s  += __shfl_xor_sync(0xffffffffu, s, o);
            ss += __shfl_xor_sync(0xffffffffu, ss, o);
        }
        if (lane == 0) { red[0][0] = s; red[1][0] = ss; }
    }
    __syncthreads();
    s = red[0][0]; ss = red[1][0];
    const float mu  = s * (1.f / 8192.f);
    const float var = ss * (1.f / 8192.f) - mu * mu;
    const float inv = rsqrtf(var + GEPS);

    if constexpr (!TRANS) {
        uint2* dst = reinterpret_cast<uint2*>(out) + (size_t)bg * 2048;
#pragma unroll
        for (int i = 0; i < 8; i++) {
            const int fi = tid + i * 256;
            const int c = g * 16 + (fi >> 7);
            const float sc = w[c] * inv;
            const float sh = bia[c] - mu * sc;
            float4 t = v[i];
            uint2 u;
            u.x = packbf(t.x * sc + sh, t.y * sc + sh);
            u.y = packbf(t.z * sc + sh, t.w * sc + sh);
            dst[fi] = u;
        }
    } else {
        __shared__ float st[16 * 516];
#pragma unroll
        for (int i = 0; i < 8; i++) {
            const int fi = tid + i * 256;
            const int cl = fi >> 7;               // local channel 0..15
            const int c = g * 16 + cl;
            const float sc = w[c] * inv;
            const float sh = bia[c] - mu * sc;
            float4 t = v[i];
            t.x = t.x * sc + sh; t.y = t.y * sc + sh;
            t.z = t.z * sc + sh; t.w = t.w * sc + sh;
            *reinterpret_cast<float4*>(&st[cl * 516 + (fi & 127) * 4]) = t;
        }
        __syncthreads();
        __nv_bfloat16* ob = out + (size_t)(bg >> 5) * NL * NC + g * 16;
        const int c4 = tid & 3;
#pragma unroll
        for (int r = 0; r < 8; r++) {
            const int l = (tid >> 2) + r * 64;
            uint2 u;
            u.x = packbf(st[(c4 * 4 + 0) * 516 + l], st[(c4 * 4 + 1) * 516 + l]);
            u.y = packbf(st[(c4 * 4 + 2) * 516 + l], st[(c4 * 4 + 3) * 516 + l]);
            *reinterpret_cast<uint2*>(ob + (size_t)l * NC + c4 * 4) = u;
        }
    }
}

// ===========================================================================
// bf16 mma.sync GEMM: C[bz](128x128) = A[M,K](K-major) * B[N,K](K-major)^T
// 8 warps (2x4), warp tile 64x32, m16n8k16, BK=64.
// 3-stage cp.async pipeline, wait_group 1 (newest group stays in flight).
// smem: A stages @ 0/16K/32K; B stages @ 48K/64K/80K. 96KB, 2 CTAs/SM.
// MODE 0: fp32 out + bias-row + residual; 1: bf16 out + bias-col;
// MODE 2: bf16 out = (acc+bias-col)*0.125 (for q).
// ===========================================================================
constexpr int GEMM_SMEM = 98304;

template<int MODE>
__global__ __launch_bounds__(256, 2) void gemm_bf16(
    const __nv_bfloat16* __restrict__ A, long long sA,
    const __nv_bfloat16* __restrict__ B, long long sB,
    void* __restrict__ Cv, long long sC,
    const float* __restrict__ bias,
    const float* __restrict__ resid, long long sR,
    int N, int K)
{
    extern __shared__ char smc[];
    const uint32_t sb = smem_u32(smc);
    const int tid = threadIdx.x, lane = tid & 31, wid = tid >> 5;
    const int wm = wid >> 2, wn = wid & 3;
    const int bz = blockIdx.z;
    const int m0 = blockIdx.y * 128, n0 = blockIdx.x * 128;
    const __nv_bfloat16* Ab = A + (size_t)sA * bz + (size_t)m0 * K;
    const __nv_bfloat16* Bb = B + (size_t)sB * bz + (size_t)n0 * K;

    auto loadTile = [&](uint32_t sbase, const __nv_bfloat16* gp) {
#pragma unroll
        for (int i = 0; i < 4; i++) {
            const int idx = tid + i * 256;
            const int row = idx >> 3, j = idx & 7;
            cp_async16(sbase + row * 128 + ((j ^ (row & 7)) << 4),
                       gp + (size_t)row * K + j * 8);
        }
    };

    float acc[4][4][4];
#pragma unroll
    for (int a = 0; a < 4; a++)
#pragma unroll
        for (int b = 0; b < 4; b++)
#pragma unroll
            for (int c = 0; c < 4; c++) acc[a][b][c] = 0.f;

    const int NT = K >> 6;              // 8 for K=512
    loadTile(sb, Ab);
    loadTile(sb + 49152, Bb);
    cp_commit();
    loadTile(sb + 16384, Ab + 64);
    loadTile(sb + 49152 + 16384, Bb + 64);
    cp_commit();

    const int g = lane >> 2, tq = lane & 3;
    const int arow = (lane & 7) + ((lane >> 3) & 1) * 8;   // A: mat&1 row-half
    const int aoff = lane >> 4;                            // A: mat>>1 chunk
    const int brow = (lane & 7) + ((lane >> 4) & 1) * 8;   // B: mat>>1 row-half
    const int boff = (lane >> 3) & 1;                      // B: mat&1 chunk

    for (int kt = 0; kt < NT; kt++) {
        if (kt + 1 < NT) cp_wait1(); else cp_wait0();
        __syncthreads();
        if (kt + 2 < NT) {
            const int st = (kt + 2) % 3;
            loadTile(sb + st * 16384, Ab + (kt + 2) * 64);
            loadTile(sb + 49152 + st * 16384, Bb + (kt + 2) * 64);
            cp_commit();
        }
        const uint32_t ab = sb + (kt % 3) * 16384;
        const uint32_t bb = sb + 49152 + (kt % 3) * 16384;
#pragma unroll
        for (int kk = 0; kk < 4; kk++) {
            uint32_t af[4][4];
#pragma unroll
            for (int mt = 0; mt < 4; mt++) {
                const int row = wm * 64 + mt * 16 + arow;
                ldsm4(af[mt], ab + row * 128 + (((kk * 2 + aoff) ^ (row & 7)) << 4));
            }
            uint32_t bfr[4][2];
#pragma unroll
            for (int bt = 0; bt < 2; bt++) {
                const int row = wn * 32 + bt * 16 + brow;
                uint32_t r[4];
                ldsm4(r, bb + row * 128 + (((kk * 2 + boff) ^ (row & 7)) << 4));
                bfr[bt * 2][0] = r[0];     bfr[bt * 2][1] = r[1];
                bfr[bt * 2 + 1][0] = r[2]; bfr[bt * 2 + 1][1] = r[3];
            }
#pragma unroll
            for (int mt = 0; mt < 4; mt++)
#pragma unroll
                for (int nt = 0; nt < 4; nt++)
                    mma_bf16(acc[mt][nt], af[mt], bfr[nt]);
        }
    }

    const int m0w = m0 + wm * 64, n0w = n0 + wn * 32;
    if constexpr (MODE == 0) {
        float* C = reinterpret_cast<float*>(Cv) + (size_t)sC * bz;
        const float* R = resid + (size_t)sR * bz;
#pragma unroll
        for (int mt = 0; mt < 4; mt++) {
            const int r0 = m0w + mt * 16 + g;
            const float bm0 = __ldg(bias + r0), bm1 = __ldg(bias + r0 + 8);
#pragma unroll
            for (int nt = 0; nt < 4; nt++) {
                const int c0 = n0w + nt * 8 + tq * 2;
                const size_t o0 = (size_t)r0 * N + c0;
                const size_t o1 = (size_t)(r0 + 8) * N + c0;
                const float2 q0 = *reinterpret_cast<const float2*>(R + o0);
                const float2 q1 = *reinterpret_cast<const float2*>(R + o1);
                float2 v0, v1;
                v0.x = acc[mt][nt][0] + bm0 + q0.x;
                v0.y = acc[mt][nt][1] + bm0 + q0.y;
                v1.x = acc[mt][nt][2] + bm1 + q1.x;
                v1.y = acc[mt][nt][3] + bm1 + q1.y;
                *reinterpret_cast<float2*>(C + o0) = v0;
                *reinterpret_cast<float2*>(C + o1) = v1;
            }
        }
    } else {
        __nv_bfloat16* C = reinterpret_cast<__nv_bfloat16*>(Cv) + (size_t)sC * bz;
        const float sc = (MODE == 2) ? 0.125f : 1.f;
#pragma unroll
        for (int mt = 0; mt < 4; mt++) {
            const int r0 = m0w + mt * 16 + g;
#pragma unroll
            for (int nt = 0; nt < 4; nt++) {
                const int c0 = n0w + nt * 8 + tq * 2;
                const float bc0 = __ldg(bias + c0), bc1 = __ldg(bias + c0 + 1);
                *reinterpret_cast<uint32_t*>(C + (size_t)r0 * N + c0) =
                    packbf((acc[mt][nt][0] + bc0) * sc, (acc[mt][nt][1] + bc1) * sc);
                *reinterpret_cast<uint32_t*>(C + (size_t)(r0 + 8) * N + c0) =
                    packbf((acc[mt][nt][2] + bc0) * sc, (acc[mt][nt][3] + bc1) * sc);
            }
        }
    }
}

// ===========================================================================
// Fused attention on mma.sync bf16, fp32 online softmax.
// grid = (L/128 t-tiles, B*NH), block = 256 (8 warps x 16 warp-private rows).
// smem (80KB): Q [128][64] @0, K x3 @16384(+8192/stage), V x3 @40960,
//              P [128][64] @65536 — bf16, 128B rows, XOR-swizzled chunks.
// 3-stage KV pipeline (wait_group 1); Q fragments hoisted to registers.
// ===========================================================================
constexpr int ATTN_SMEM = 81920;

__global__ __launch_bounds__(256, 2) void attn_bf16(
    const __nv_bfloat16* __restrict__ q, const __nv_bfloat16* __restrict__ kv,
    __nv_bfloat16* __restrict__ outaT)
{
    extern __shared__ char smc[];
    const uint32_t sb = smem_u32(smc);
    const int tid = threadIdx.x, lane = tid & 31, w = tid >> 5;
    const int t0 = blockIdx.x * 128;
    const int bh = blockIdx.y, b = bh >> 3, h = bh & 7;
    const int g = lane >> 2, tq = lane & 3;
    const int tb = w * 16;

    // Q tile: qT[b*NL + t0 + t][h*64 + d]  (rows t, d contiguous)
    {
        const __nv_bfloat16* qb = q + ((size_t)b * NL + t0) * NC + h * 64;
#pragma unroll
        for (int i = 0; i < 4; i++) {
            const int idx = tid + i * 256;
            const int t = idx >> 3, j = idx & 7;
            cp_async16(sb + t * 128 + ((j ^ (t & 7)) << 4),
                       qb + (size_t)t * NC + j * 8);
        }
    }
    const __nv_bfloat16* kvb = kv + (size_t)b * NC * 1024;
    auto loadKV = [&](int sc, int buf) {
#pragma unroll
        for (int i = 0; i < 2; i++) {
            const int idx = tid + i * 256;
            const int d = idx >> 3, j = idx & 7;
            const int ck = 32 * h + (d >> 1);
            const int ob = (d & 1) * 512 + sc * 64 + j * 8;
            const __nv_bfloat16* srcK = kvb + (size_t)ck * 1024 + ob;
            const uint32_t soff = d * 128 + ((j ^ (d & 7)) << 4);
            cp_async16(sb + 16384 + buf * 8192 + soff, srcK);
            cp_async16(sb + 40960 + buf * 8192 + soff, srcK + 256 * 1024);
        }
    };
    loadKV(0, 0);
    cp_commit();           // group 0: Q + KV chunk 0
    loadKV(1, 1);
    cp_commit();           // group 1: KV chunk 1

    float m0 = -1e30f, m1 = -1e30f, l0 = 0.f, l1 = 0.f;
    float O[8][4];
#pragma unroll
    for (int j = 0; j < 8; j++)
#pragma unroll
        for (int k = 0; k < 4; k++) O[j][k] = 0.f;

    const int arow = tb + (lane & 7) + ((lane >> 3) & 1) * 8; // A frag rows (Q/P)
    const int aoff = lane >> 4;
    const int ktrow = (lane & 7) + ((lane >> 3) & 1) * 8;     // K-trans: d rows
    const int ktoff = lane >> 4;                               // K-trans: s chunk
    const int vrow = (lane & 7) + ((lane >> 4) & 1) * 8;      // V: d row-half
    const int voff = (lane >> 3) & 1;                          // V: s chunk

    uint32_t qf[4][4];     // hoisted Q fragments (filled at sc==0)

    for (int sc = 0; sc < 8; sc++) {
        if (sc + 1 < 8) cp_wait1(); else cp_wait0();
        __syncthreads();
        if (sc + 2 < 8) {
            loadKV(sc + 2, (sc + 2) % 3);
            cp_commit();
        }
        if (sc == 0) {
#pragma unroll
            for (int kk = 0; kk < 4; kk++)
                ldsm4(qf[kk], sb + arow * 128 + (((kk * 2 + aoff) ^ (arow & 7)) << 4));
        }
        const uint32_t kbK = sb + 16384 + (sc % 3) * 8192;
        const uint32_t kbV = sb + 40960 + (sc % 3) * 8192;

        // ---- S = Q K^T  (warp: 16t x 64s; k = d over 4 k16 groups) ----
        float S[8][4];
#pragma unroll
        for (int j = 0; j < 8; j++)
#pragma unroll
            for (int k = 0; k < 4; k++) S[j][k] = 0.f;

#pragma unroll
        for (int kk = 0; kk < 4; kk++) {
            uint32_t bfr[8][2];
#pragma unroll
            for (int st = 0; st < 4; st++) {
                const int drow = kk * 16 + ktrow;
                uint32_t r[4];
                ldsm4t(r, kbK + drow * 128 + (((st * 2 + ktoff) ^ (drow & 7)) << 4));
                bfr[st * 2][0] = r[0];     bfr[st * 2][1] = r[1];
                bfr[st * 2 + 1][0] = r[2]; bfr[st * 2 + 1][1] = r[3];
            }
#pragma unroll
            for (int j = 0; j < 8; j++) mma_bf16(S[j], qf[kk], bfr[j]);
        }

        // ---- online softmax (warp-private rows; quad reductions only) ----
        float mx0 = -1e30f, mx1 = -1e30f;
#pragma unroll
        for (int j = 0; j < 8; j++) {
            mx0 = fmaxf(mx0, fmaxf(S[j][0], S[j][1]));
            mx1 = fmaxf(mx1, fmaxf(S[j][2], S[j][3]));
        }
        mx0 = qmax(mx0); mx1 = qmax(mx1);
        const float mn0 = fmaxf(m0, mx0), mn1 = fmaxf(m1, mx1);
        const float al0 = __expf(m0 - mn0), al1 = __expf(m1 - mn1);
        m0 = mn0; m1 = mn1;

        float rs0 = 0.f, rs1 = 0.f;
        const int t1r = tb + g, t2r = tb + g + 8;
        char* P1 = smc + 65536 + t1r * 128 + 4 * tq;
        char* P2 = smc + 65536 + t2r * 128 + 4 * tq;
        const int tsw = t1r & 7;
#pragma unroll
        for (int j = 0; j < 8; j++) {
            const float p0 = __expf(S[j][0] - mn0);
            const float p1 = __expf(S[j][1] - mn0);
            const float p2 = __expf(S[j][2] - mn1);
            const float p3 = __expf(S[j][3] - mn1);
            rs0 += p0 + p1; rs1 += p2 + p3;
            *reinterpret_cast<uint32_t*>(P1 + ((j ^ tsw) << 4)) = packbf(p0, p1);
            *reinterpret_cast<uint32_t*>(P2 + ((j ^ tsw) << 4)) = packbf(p2, p3);
        }
        rs0 = qsum(rs0); rs1 = qsum(rs1);
        l0 = l0 * al0 + rs0;
        l1 = l1 * al1 + rs1;
#pragma unroll
        for (int j = 0; j < 8; j++) {
            O[j][0] *= al0; O[j][1] *= al0;
            O[j][2] *= al1; O[j][3] *= al1;
        }
        __syncwarp();

        // ---- O += P V  (warp: 16t x 64d; k = s over 4 k16 groups) ----
        const uint32_t pb = sb + 65536;
#pragma unroll
        for (int kk = 0; kk < 4; kk++) {
            uint32_t af[4];
            ldsm4(af, pb + arow * 128 + (((kk * 2 + aoff) ^ (arow & 7)) << 4));
            uint32_t bfr[8][2];
#pragma unroll
            for (int dt = 0; dt < 4; dt++) {
                const int row = dt * 16 + vrow;
                uint32_t r[4];
                ldsm4(r, kbV + row * 128 + (((kk * 2 + voff) ^ (row & 7)) << 4));
                bfr[dt * 2][0] = r[0];     bfr[dt * 2][1] = r[1];
                bfr[dt * 2 + 1][0] = r[2]; bfr[dt * 2 + 1][1] = r[3];
            }
#pragma unroll
            for (int j = 0; j < 8; j++) mma_bf16(O[j], af, bfr[j]);
        }
    }

    // ---- finalize + store: aT[b][t0+t][h*64 + d] (bf16 pairs) ----
    const float i0 = 1.f / l0, i1 = 1.f / l1;
    __nv_bfloat16* ab = outaT + ((size_t)b * NL + t0 + tb) * NC + h * 64;
#pragma unroll
    for (int j = 0; j < 8; j++) {
        *reinterpret_cast<uint32_t*>(ab + (size_t)g * NC + j * 8 + tq * 2) =
            packbf(O[j][0] * i0, O[j][1] * i0);
        *reinterpret_cast<uint32_t*>(ab + (size_t)(g + 8) * NC + j * 8 + tq * 2) =
            packbf(O[j][2] * i1, O[j][3] * i1);
    }
}

// ===========================================================================
extern "C" void kernel_launch(void* const* d_in, const int* in_sizes, int n_in,
                              void* d_out, int out_size)
{
    const float* x      = (const float*)d_in[0];
    const float* ctx    = (const float*)d_in[1];
    const float* norm_w = (const float*)d_in[2];
    const float* norm_b = (const float*)d_in[3];
    const float* q_w    = (const float*)d_in[4];
    const float* q_b    = (const float*)d_in[5];
    const float* kv_w   = (const float*)d_in[6];
    const float* kv_b   = (const float*)d_in[7];
    const float* proj_w = (const float*)d_in[8];
    const float* proj_b = (const float*)d_in[9];
    float* out = (float*)d_out;

    __nv_bfloat16 *xnT, *cn, *qp, *kvp, *aT, *qwb, *kvwb, *pwb;
    cudaGetSymbolAddress((void**)&xnT,  g_xnT);
    cudaGetSymbolAddress((void**)&cn,   g_cn);
    cudaGetSymbolAddress((void**)&qp,   g_q);
    cudaGetSymbolAddress((void**)&kvp,  g_kv);
    cudaGetSymbolAddress((void**)&aT,   g_aT);
    cudaGetSymbolAddress((void**)&qwb,  g_qw);
    cudaGetSymbolAddress((void**)&kvwb, g_kvw);
    cudaGetSymbolAddress((void**)&pwb,  g_pw);

    cudaFuncSetAttribute(attn_bf16,
                         cudaFuncAttributeMaxDynamicSharedMemorySize, ATTN_SMEM);
    cudaFuncSetAttribute(gemm_bf16<0>,
                         cudaFuncAttributeMaxDynamicSharedMemorySize, GEMM_SMEM);
    cudaFuncSetAttribute(gemm_bf16<1>,
                         cudaFuncAttributeMaxDynamicSharedMemorySize, GEMM_SMEM);
    cudaFuncSetAttribute(gemm_bf16<2>,
                         cudaFuncAttributeMaxDynamicSharedMemorySize, GEMM_SMEM);

    // Weights -> bf16
    cvt_bf16_kernel<<<256, 256>>>(q_w,    qwb,  NC * NC / 4);
    cvt_bf16_kernel<<<512, 256>>>(kv_w,   kvwb, 2 * NC * NC / 4);
    cvt_bf16_kernel<<<256, 256>>>(proj_w, pwb,  NC * NC / 4);

    // GroupNorm: x -> xnT bf16 [l][c]; ctx -> cn bf16 [c][l]
    groupnorm_kernel<true ><<<NB * NG, 256>>>(x,   norm_w, norm_b, xnT);
    groupnorm_kernel<false><<<NB * NG, 256>>>(ctx, norm_w, norm_b, cn);

    // qT[b,l,o] = (xnT(l,c) . q_w(o,c)^T + q_b[o]) * 0.125   -> bf16
    gemm_bf16<2><<<dim3(4, 4, NB), 256, GEMM_SMEM>>>(
        xnT, (long long)NL * NC, qwb, 0, qp, (long long)NL * NC,
        q_b, nullptr, 0, NC, NC);

    // kv[b,c,o] = cn(c,l) . kv_w(o,l)^T + kv_b[o]            -> bf16
    gemm_bf16<1><<<dim3(8, 4, NB), 256, GEMM_SMEM>>>(
        cn, (long long)NC * NC, kvwb, 0, kvp, (long long)NC * 2 * NC,
        kv_b, nullptr, 0, 2 * NC, NC);

    // attention -> aT[b,l,c] bf16
    attn_bf16<<<dim3(4, NB * 8), 256, ATTN_SMEM>>>(qp, kvp, aT);

    // out[b,o,l] = x + proj_w(o,c) . aT(l,c)^T + proj_b[o]   (fp32)
    gemm_bf16<0><<<dim3(4, 4, NB), 256, GEMM_SMEM>>>(
        pwb, 0, aT, (long long)NL * NC, out, (long long)NC * NL,
        proj_b, x, (long long)NC * NL, NL, NC);
}

// round 10
// speedup vs baseline: 1.0786x; 1.0786x over previous
#include <cuda_runtime.h>
#include <cuda_bf16.h>
#include <math.h>
#include <stdint.h>

constexpr int NB = 32;      // batch
constexpr int NC = 512;     // channels
constexpr int NL = 512;     // length
constexpr int NG = 32;      // groups
constexpr float GEPS = 1e-5f;

// Scratch (static device globals: allocation-free, graph-safe) — bf16
__device__ __nv_bfloat16 g_xnT[NB * NL * NC];     // GN(x), TRANSPOSED [l][c]
__device__ __nv_bfloat16 g_cn [NB * NC * NC];     // GN(ctx), natural [c][l]
__device__ __nv_bfloat16 g_q  [NB * NL * NC];     // qT [l][o], pre-scaled by 1/8
__device__ __nv_bfloat16 g_kv [NB * NC * 2 * NC]; // kv [c][o]
__device__ __nv_bfloat16 g_aT [NB * NL * NC];     // attn out, TRANSPOSED [l][c]
__device__ __nv_bfloat16 g_qw [NC * NC];          // bf16 weights
__device__ __nv_bfloat16 g_kvw[2 * NC * NC];
__device__ __nv_bfloat16 g_pw [NC * NC];

// ===========================================================================
// PTX helpers (plain sm_100-compatible)
// ===========================================================================
__device__ __forceinline__ uint32_t smem_u32(const void* p) {
    uint32_t a;
    asm("{ .reg .u64 t; cvta.to.shared.u64 t, %1; cvt.u32.u64 %0, t; }"
        : "=r"(a) : "l"(p));
    return a;
}
__device__ __forceinline__ void cp_async16(uint32_t dst, const void* src) {
    asm volatile("{ .reg .u64 g; cvta.to.global.u64 g, %1; "
                 "cp.async.cg.shared.global [%0], [g], 16; }"
                 :: "r"(dst), "l"(src) : "memory");
}
__device__ __forceinline__ void cp_commit() {
    asm volatile("cp.async.commit_group;" ::: "memory");
}
__device__ __forceinline__ void cp_wait1() {
    asm volatile("cp.async.wait_group 1;" ::: "memory");
}
__device__ __forceinline__ void cp_wait0() {
    asm volatile("cp.async.wait_group 0;" ::: "memory");
}
__device__ __forceinline__ void ldsm4(uint32_t* r, uint32_t a) {
    asm volatile("ldmatrix.sync.aligned.m8n8.x4.shared.b16 {%0,%1,%2,%3}, [%4];"
                 : "=r"(r[0]), "=r"(r[1]), "=r"(r[2]), "=r"(r[3]) : "r"(a));
}
__device__ __forceinline__ void ldsm4t(uint32_t* r, uint32_t a) {
    asm volatile("ldmatrix.sync.aligned.m8n8.x4.trans.shared.b16 {%0,%1,%2,%3}, [%4];"
                 : "=r"(r[0]), "=r"(r[1]), "=r"(r[2]), "=r"(r[3]) : "r"(a));
}
__device__ __forceinline__ void mma_bf16(float* c, const uint32_t* a, const uint32_t* b) {
    asm volatile(
        "mma.sync.aligned.m16n8k16.row.col.f32.bf16.bf16.f32 "
        "{%0,%1,%2,%3}, {%4,%5,%6,%7}, {%8,%9}, {%0,%1,%2,%3};"
        : "+f"(c[0]), "+f"(c[1]), "+f"(c[2]), "+f"(c[3])
        : "r"(a[0]), "r"(a[1]), "r"(a[2]), "r"(a[3]), "r"(b[0]), "r"(b[1]));
}
__device__ __forceinline__ uint32_t packbf(float lo, float hi) {
    __nv_bfloat162 h = __floats2bfloat162_rn(lo, hi);
    return *reinterpret_cast<uint32_t*>(&h);
}
__device__ __forceinline__ float qmax(float v) {
    v = fmaxf(v, __shfl_xor_sync(0xffffffffu, v, 1));
    v = fmaxf(v, __shfl_xor_sync(0xffffffffu, v, 2));
    return v;
}
__device__ __forceinline__ float qsum(float v) {
    v += __shfl_xor_sync(0xffffffffu, v, 1);
    v += __shfl_xor_sync(0xffffffffu, v, 2);
    return v;
}

// ===========================================================================
// Fused GroupNorm(x, TRANS) + GroupNorm(ctx) + weight cvt, one launch.
// grid = 2560 x 512 threads:
//   blocks [0,1024):    GN(x)   -> xnT bf16 [l][c]
//   blocks [1024,2048): GN(ctx) -> cn  bf16 [c][l]
//   blocks [2048,2560): fp32->bf16 weight conversion (1 uint2/thread)
// ===========================================================================
__global__ __launch_bounds__(512) void gn_cvt_kernel(
    const float* __restrict__ x, const float* __restrict__ ctx,
    const float* __restrict__ w, const float* __restrict__ bia,
    const float* __restrict__ q_w, const float* __restrict__ kv_w,
    const float* __restrict__ proj_w,
    __nv_bfloat16* __restrict__ xnT, __nv_bfloat16* __restrict__ cn,
    __nv_bfloat16* __restrict__ qwb, __nv_bfloat16* __restrict__ kvwb,
    __nv_bfloat16* __restrict__ pwb)
{
    __shared__ float st[16 * 516];          // TRANS staging (33 KB)
    __shared__ float red[2][16];
    const int bid = blockIdx.x;
    const int tid = threadIdx.x;

    if (bid >= 2048) {
        // ---- weight cvt: 512 blocks x 512 threads x 4 elems ----
        const int i = (bid - 2048) * 512 + tid;        // 0..262143 quads
        const float* s; __nv_bfloat16* d; int off;
        if (i < 65536)        { s = q_w;    d = qwb;  off = i; }
        else if (i < 196608)  { s = kv_w;   d = kvwb; off = i - 65536; }
        else                  { s = proj_w; d = pwb;  off = i - 196608; }
        const float4 v = reinterpret_cast<const float4*>(s)[off];
        uint2 u;
        u.x = packbf(v.x, v.y);
        u.y = packbf(v.z, v.w);
        reinterpret_cast<uint2*>(d)[off] = u;
        return;
    }

    const bool isX = bid < 1024;
    const int bg = bid & 1023;
    const int g = bg % NG;
    const float4* src = reinterpret_cast<const float4*>(isX ? x : ctx)
                        + (size_t)bg * 2048;

    float s = 0.f, ss = 0.f;
    float4 v[4];
#pragma unroll
    for (int i = 0; i < 4; i++) {
        v[i] = src[tid + i * 512];
        s  += v[i].x + v[i].y + v[i].z + v[i].w;
        ss += v[i].x * v[i].x + v[i].y * v[i].y + v[i].z * v[i].z + v[i].w * v[i].w;
    }
#pragma unroll
    for (int o = 16; o > 0; o >>= 1) {
        s  += __shfl_xor_sync(0xffffffffu, s, o);
        ss += __shfl_xor_sync(0xffffffffu, ss, o);
    }
    const int warp = tid >> 5, lane = tid & 31;
    if (lane == 0) { red[0][warp] = s; red[1][warp] = ss; }
    __syncthreads();
    if (warp == 0) {
        s = red[0][lane & 15]; ss = red[1][lane & 15];
#pragma unroll
        for (int o = 8; o > 0; o >>= 1) {
            s  += __shfl_xor_sync(0xffffffffu, s, o);
            ss += __shfl_xor_sync(0xffffffffu, ss, o);
        }
        if (lane == 0) { red[0][0] = s; red[1][0] = ss; }
    }
    __syncthreads();
    s = red[0][0]; ss = red[1][0];
    const float mu  = s * (1.f / 8192.f);
    const float var = ss * (1.f / 8192.f) - mu * mu;
    const float inv = rsqrtf(var + GEPS);

    if (!isX) {
        // natural [c][l] bf16
        uint2* dst = reinterpret_cast<uint2*>(cn) + (size_t)bg * 2048;
#pragma unroll
        for (int i = 0; i < 4; i++) {
            const int fi = tid + i * 512;
            const int c = g * 16 + (fi >> 7);
            const float sc = w[c] * inv;
            const float sh = bia[c] - mu * sc;
            float4 t = v[i];
            uint2 u;
            u.x = packbf(t.x * sc + sh, t.y * sc + sh);
            u.y = packbf(t.z * sc + sh, t.w * sc + sh);
            dst[fi] = u;
        }
    } else {
        // TRANSPOSED [l][c] bf16 via smem staging
#pragma unroll
        for (int i = 0; i < 4; i++) {
            const int fi = tid + i * 512;
            const int cl = fi >> 7;               // local channel 0..15
            const int c = g * 16 + cl;
            const float sc = w[c] * inv;
            const float sh = bia[c] - mu * sc;
            float4 t = v[i];
            t.x = t.x * sc + sh; t.y = t.y * sc + sh;
            t.z = t.z * sc + sh; t.w = t.w * sc + sh;
            *reinterpret_cast<float4*>(&st[cl * 516 + (fi & 127) * 4]) = t;
        }
        __syncthreads();
        __nv_bfloat16* ob = xnT + (size_t)(bg >> 5) * NL * NC + g * 16;
        const int c4 = tid & 3;
#pragma unroll
        for (int r = 0; r < 4; r++) {
            const int l = (tid >> 2) + r * 128;
            uint2 u;
            u.x = packbf(st[(c4 * 4 + 0) * 516 + l], st[(c4 * 4 + 1) * 516 + l]);
            u.y = packbf(st[(c4 * 4 + 2) * 516 + l], st[(c4 * 4 + 3) * 516 + l]);
            *reinterpret_cast<uint2*>(ob + (size_t)l * NC + c4 * 4) = u;
        }
    }
}

// ===========================================================================
// Fused q-GEMM + kv-GEMM, one launch. grid (8, 4, 48):
//   z in [0,32):  kv[b,c,o] = cn(c,l) . kv_w(o,l)^T + kv_b[o]        (N=1024)
//   z in [32,48): qT[b,l,o] = (xnT(l,c).q_w(o,c)^T + q_b[o]) * 1/8   (N=512)
// Mainloop: 8 warps (2x4), warp tile 64x32, m16n8k16, BK=64,
// 3-stage cp.async pipeline. smem 96KB, 2 CTAs/SM. bf16 epilogue.
// ===========================================================================
constexpr int GEMM_SMEM = 98304;

__global__ __launch_bounds__(256, 2) void gemm_qkv(
    const __nv_bfloat16* __restrict__ xnT, const __nv_bfloat16* __restrict__ qwb,
    const __nv_bfloat16* __restrict__ cn,  const __nv_bfloat16* __restrict__ kvwb,
    __nv_bfloat16* __restrict__ qp, __nv_bfloat16* __restrict__ kvp,
    const float* __restrict__ q_b, const float* __restrict__ kv_b)
{
    extern __shared__ char smc[];
    const uint32_t sb = smem_u32(smc);
    const int tid = threadIdx.x, lane = tid & 31, wid = tid >> 5;
    const int wm = wid >> 2, wn = wid & 3;
    const int z = blockIdx.z;
    const bool isQ = z >= 32;
    const int m0 = blockIdx.y * 128;

    int bz, n0, N;
    const __nv_bfloat16 *Ab, *Bb;
    __nv_bfloat16* Cb;
    const float* bias;
    float scl;
    if (isQ) {
        bz = (z - 32) * 2 + (blockIdx.x >> 2);
        n0 = (blockIdx.x & 3) * 128;
        N = 512;
        Ab = xnT + (size_t)bz * NL * NC + (size_t)m0 * 512;
        Bb = qwb + (size_t)n0 * 512;
        Cb = qp + (size_t)bz * NL * NC;
        bias = q_b;
        scl = 0.125f;
    } else {
        bz = z;
        n0 = blockIdx.x * 128;
        N = 1024;
        Ab = cn + (size_t)bz * NC * NC + (size_t)m0 * 512;
        Bb = kvwb + (size_t)n0 * 512;
        Cb = kvp + (size_t)bz * NC * 1024;
        bias = kv_b;
        scl = 1.f;
    }
    constexpr int K = 512;

    auto loadTile = [&](uint32_t sbase, const __nv_bfloat16* gp) {
#pragma unroll
        for (int i = 0; i < 4; i++) {
            const int idx = tid + i * 256;
            const int row = idx >> 3, j = idx & 7;
            cp_async16(sbase + row * 128 + ((j ^ (row & 7)) << 4),
                       gp + (size_t)row * K + j * 8);
        }
    };

    float acc[4][4][4];
#pragma unroll
    for (int a = 0; a < 4; a++)
#pragma unroll
        for (int b = 0; b < 4; b++)
#pragma unroll
            for (int c = 0; c < 4; c++) acc[a][b][c] = 0.f;

    constexpr int NT = K >> 6;          // 8
    loadTile(sb, Ab);
    loadTile(sb + 49152, Bb);
    cp_commit();
    loadTile(sb + 16384, Ab + 64);
    loadTile(sb + 49152 + 16384, Bb + 64);
    cp_commit();

    const int g = lane >> 2, tq = lane & 3;
    const int arow = (lane & 7) + ((lane >> 3) & 1) * 8;
    const int aoff = lane >> 4;
    const int brow = (lane & 7) + ((lane >> 4) & 1) * 8;
    const int boff = (lane >> 3) & 1;

    for (int kt = 0; kt < NT; kt++) {
        if (kt + 1 < NT) cp_wait1(); else cp_wait0();
        __syncthreads();
        if (kt + 2 < NT) {
            const int st = (kt + 2) % 3;
            loadTile(sb + st * 16384, Ab + (kt + 2) * 64);
            loadTile(sb + 49152 + st * 16384, Bb + (kt + 2) * 64);
            cp_commit();
        }
        const uint32_t ab = sb + (kt % 3) * 16384;
        const uint32_t bb = sb + 49152 + (kt % 3) * 16384;
#pragma unroll
        for (int kk = 0; kk < 4; kk++) {
            uint32_t af[4][4];
#pragma unroll
            for (int mt = 0; mt < 4; mt++) {
                const int row = wm * 64 + mt * 16 + arow;
                ldsm4(af[mt], ab + row * 128 + (((kk * 2 + aoff) ^ (row & 7)) << 4));
            }
            uint32_t bfr[4][2];
#pragma unroll
            for (int bt = 0; bt < 2; bt++) {
                const int row = wn * 32 + bt * 16 + brow;
                uint32_t r[4];
                ldsm4(r, bb + row * 128 + (((kk * 2 + boff) ^ (row & 7)) << 4));
                bfr[bt * 2][0] = r[0];     bfr[bt * 2][1] = r[1];
                bfr[bt * 2 + 1][0] = r[2]; bfr[bt * 2 + 1][1] = r[3];
            }
#pragma unroll
            for (int mt = 0; mt < 4; mt++)
#pragma unroll
                for (int nt = 0; nt < 4; nt++)
                    mma_bf16(acc[mt][nt], af[mt], bfr[nt]);
        }
    }

    const int m0w = m0 + wm * 64, n0w = n0 + wn * 32;
#pragma unroll
    for (int mt = 0; mt < 4; mt++) {
        const int r0 = m0w + mt * 16 + g;
#pragma unroll
        for (int nt = 0; nt < 4; nt++) {
            const int c0 = n0w + nt * 8 + tq * 2;
            const float bc0 = __ldg(bias + c0), bc1 = __ldg(bias + c0 + 1);
            *reinterpret_cast<uint32_t*>(Cb + (size_t)r0 * N + c0) =
                packbf((acc[mt][nt][0] + bc0) * scl, (acc[mt][nt][1] + bc1) * scl);
            *reinterpret_cast<uint32_t*>(Cb + (size_t)(r0 + 8) * N + c0) =
                packbf((acc[mt][nt][2] + bc0) * scl, (acc[mt][nt][3] + bc1) * scl);
        }
    }
}

// ===========================================================================
// proj GEMM: out[b,o,l] = x + proj_w(o,c) . aT(l,c)^T + proj_b[o]  (fp32 out)
// Same mainloop as gemm_qkv; fp32 epilogue with bias-row + residual.
// ===========================================================================
__global__ __launch_bounds__(256, 2) void gemm_proj(
    const __nv_bfloat16* __restrict__ A,      // proj_w bf16 [o][c]
    const __nv_bfloat16* __restrict__ B,      // aT bf16 [b][l][c]
    float* __restrict__ C,                    // out [b][o][l]
    const float* __restrict__ bias,           // proj_b
    const float* __restrict__ resid)          // x [b][o][l]
{
    extern __shared__ char smc[];
    const uint32_t sb = smem_u32(smc);
    const int tid = threadIdx.x, lane = tid & 31, wid = tid >> 5;
    const int wm = wid >> 2, wn = wid & 3;
    const int bz = blockIdx.z;
    const int m0 = blockIdx.y * 128, n0 = blockIdx.x * 128;
    constexpr int K = 512, N = 512;
    const __nv_bfloat16* Ab = A + (size_t)m0 * K;
    const __nv_bfloat16* Bb = B + (size_t)bz * NL * NC + (size_t)n0 * K;

    auto loadTile = [&](uint32_t sbase, const __nv_bfloat16* gp) {
#pragma unroll
        for (int i = 0; i < 4; i++) {
            const int idx = tid + i * 256;
            const int row = idx >> 3, j = idx & 7;
            cp_async16(sbase + row * 128 + ((j ^ (row & 7)) << 4),
                       gp + (size_t)row * K + j * 8);
        }
    };

    float acc[4][4][4];
#pragma unroll
    for (int a = 0; a < 4; a++)
#pragma unroll
        for (int b = 0; b < 4; b++)
#pragma unroll
            for (int c = 0; c < 4; c++) acc[a][b][c] = 0.f;

    constexpr int NT = K >> 6;
    loadTile(sb, Ab);
    loadTile(sb + 49152, Bb);
    cp_commit();
    loadTile(sb + 16384, Ab + 64);
    loadTile(sb + 49152 + 16384, Bb + 64);
    cp_commit();

    const int g = lane >> 2, tq = lane & 3;
    const int arow = (lane & 7) + ((lane >> 3) & 1) * 8;
    const int aoff = lane >> 4;
    const int brow = (lane & 7) + ((lane >> 4) & 1) * 8;
    const int boff = (lane >> 3) & 1;

    for (int kt = 0; kt < NT; kt++) {
        if (kt + 1 < NT) cp_wait1(); else cp_wait0();
        __syncthreads();
        if (kt + 2 < NT) {
            const int st = (kt + 2) % 3;
            loadTile(sb + st * 16384, Ab + (kt + 2) * 64);
            loadTile(sb + 49152 + st * 16384, Bb + (kt + 2) * 64);
            cp_commit();
        }
        const uint32_t ab = sb + (kt % 3) * 16384;
        const uint32_t bb = sb + 49152 + (kt % 3) * 16384;
#pragma unroll
        for (int kk = 0; kk < 4; kk++) {
            uint32_t af[4][4];
#pragma unroll
            for (int mt = 0; mt < 4; mt++) {
                const int row = wm * 64 + mt * 16 + arow;
                ldsm4(af[mt], ab + row * 128 + (((kk * 2 + aoff) ^ (row & 7)) << 4));
            }
            uint32_t bfr[4][2];
#pragma unroll
            for (int bt = 0; bt < 2; bt++) {
                const int row = wn * 32 + bt * 16 + brow;
                uint32_t r[4];
                ldsm4(r, bb + row * 128 + (((kk * 2 + boff) ^ (row & 7)) << 4));
                bfr[bt * 2][0] = r[0];     bfr[bt * 2][1] = r[1];
                bfr[bt * 2 + 1][0] = r[2]; bfr[bt * 2 + 1][1] = r[3];
            }
#pragma unroll
            for (int mt = 0; mt < 4; mt++)
#pragma unroll
                for (int nt = 0; nt < 4; nt++)
                    mma_bf16(acc[mt][nt], af[mt], bfr[nt]);
        }
    }

    float* Cb = C + (size_t)bz * NC * NL;
    const float* Rb = resid + (size_t)bz * NC * NL;
    const int m0w = m0 + wm * 64, n0w = n0 + wn * 32;
#pragma unroll
    for (int mt = 0; mt < 4; mt++) {
        const int r0 = m0w + mt * 16 + g;
        const float bm0 = __ldg(bias + r0), bm1 = __ldg(bias + r0 + 8);
#pragma unroll
        for (int nt = 0; nt < 4; nt++) {
            const int c0 = n0w + nt * 8 + tq * 2;
            const size_t o0 = (size_t)r0 * N + c0;
            const size_t o1 = (size_t)(r0 + 8) * N + c0;
            const float2 q0 = *reinterpret_cast<const float2*>(Rb + o0);
            const float2 q1 = *reinterpret_cast<const float2*>(Rb + o1);
            float2 v0, v1;
            v0.x = acc[mt][nt][0] + bm0 + q0.x;
            v0.y = acc[mt][nt][1] + bm0 + q0.y;
            v1.x = acc[mt][nt][2] + bm1 + q1.x;
            v1.y = acc[mt][nt][3] + bm1 + q1.y;
            *reinterpret_cast<float2*>(Cb + o0) = v0;
            *reinterpret_cast<float2*>(Cb + o1) = v1;
        }
    }
}

// ===========================================================================
// Fused attention on mma.sync bf16, fp32 online softmax. (unchanged from R9)
// grid = (L/128 t-tiles, B*NH), block = 256 (8 warps x 16 warp-private rows).
// smem (80KB): Q [128][64] @0, K x3 @16384(+8192/stage), V x3 @40960,
//              P [128][64] @65536 — bf16, 128B rows, XOR-swizzled chunks.
// ===========================================================================
constexpr int ATTN_SMEM = 81920;

__global__ __launch_bounds__(256, 2) void attn_bf16(
    const __nv_bfloat16* __restrict__ q, const __nv_bfloat16* __restrict__ kv,
    __nv_bfloat16* __restrict__ outaT)
{
    extern __shared__ char smc[];
    const uint32_t sb = smem_u32(smc);
    const int tid = threadIdx.x, lane = tid & 31, w = tid >> 5;
    const int t0 = blockIdx.x * 128;
    const int bh = blockIdx.y, b = bh >> 3, h = bh & 7;
    const int g = lane >> 2, tq = lane & 3;
    const int tb = w * 16;

    {
        const __nv_bfloat16* qb = q + ((size_t)b * NL + t0) * NC + h * 64;
#pragma unroll
        for (int i = 0; i < 4; i++) {
            const int idx = tid + i * 256;
            const int t = idx >> 3, j = idx & 7;
            cp_async16(sb + t * 128 + ((j ^ (t & 7)) << 4),
                       qb + (size_t)t * NC + j * 8);
        }
    }
    const __nv_bfloat16* kvb = kv + (size_t)b * NC * 1024;
    auto loadKV = [&](int sc, int buf) {
#pragma unroll
        for (int i = 0; i < 2; i++) {
            const int idx = tid + i * 256;
            const int d = idx >> 3, j = idx & 7;
            const int ck = 32 * h + (d >> 1);
            const int ob = (d & 1) * 512 + sc * 64 + j * 8;
            const __nv_bfloat16* srcK = kvb + (size_t)ck * 1024 + ob;
            const uint32_t soff = d * 128 + ((j ^ (d & 7)) << 4);
            cp_async16(sb + 16384 + buf * 8192 + soff, srcK);
            cp_async16(sb + 40960 + buf * 8192 + soff, srcK + 256 * 1024);
        }
    };
    loadKV(0, 0);
    cp_commit();
    loadKV(1, 1);
    cp_commit();

    float m0 = -1e30f, m1 = -1e30f, l0 = 0.f, l1 = 0.f;
    float O[8][4];
#pragma unroll
    for (int j = 0; j < 8; j++)
#pragma unroll
        for (int k = 0; k < 4; k++) O[j][k] = 0.f;

    const int arow = tb + (lane & 7) + ((lane >> 3) & 1) * 8;
    const int aoff = lane >> 4;
    const int ktrow = (lane & 7) + ((lane >> 3) & 1) * 8;
    const int ktoff = lane >> 4;
    const int vrow = (lane & 7) + ((lane >> 4) & 1) * 8;
    const int voff = (lane >> 3) & 1;

    uint32_t qf[4][4];

    for (int sc = 0; sc < 8; sc++) {
        if (sc + 1 < 8) cp_wait1(); else cp_wait0();
        __syncthreads();
        if (sc + 2 < 8) {
            loadKV(sc + 2, (sc + 2) % 3);
            cp_commit();
        }
        if (sc == 0) {
#pragma unroll
            for (int kk = 0; kk < 4; kk++)
                ldsm4(qf[kk], sb + arow * 128 + (((kk * 2 + aoff) ^ (arow & 7)) << 4));
        }
        const uint32_t kbK = sb + 16384 + (sc % 3) * 8192;
        const uint32_t kbV = sb + 40960 + (sc % 3) * 8192;

        float S[8][4];
#pragma unroll
        for (int j = 0; j < 8; j++)
#pragma unroll
            for (int k = 0; k < 4; k++) S[j][k] = 0.f;

#pragma unroll
        for (int kk = 0; kk < 4; kk++) {
            uint32_t bfr[8][2];
#pragma unroll
            for (int st = 0; st < 4; st++) {
                const int drow = kk * 16 + ktrow;
                uint32_t r[4];
                ldsm4t(r, kbK + drow * 128 + (((st * 2 + ktoff) ^ (drow & 7)) << 4));
                bfr[st * 2][0] = r[0];     bfr[st * 2][1] = r[1];
                bfr[st * 2 + 1][0] = r[2]; bfr[st * 2 + 1][1] = r[3];
            }
#pragma unroll
            for (int j = 0; j < 8; j++) mma_bf16(S[j], qf[kk], bfr[j]);
        }

        float mx0 = -1e30f, mx1 = -1e30f;
#pragma unroll
        for (int j = 0; j < 8; j++) {
            mx0 = fmaxf(mx0, fmaxf(S[j][0], S[j][1]));
            mx1 = fmaxf(mx1, fmaxf(S[j][2], S[j][3]));
        }
        mx0 = qmax(mx0); mx1 = qmax(mx1);
        const float mn0 = fmaxf(m0, mx0), mn1 = fmaxf(m1, mx1);
        const float al0 = __expf(m0 - mn0), al1 = __expf(m1 - mn1);
        m0 = mn0; m1 = mn1;

        float rs0 = 0.f, rs1 = 0.f;
        const int t1r = tb + g, t2r = tb + g + 8;
        char* P1 = smc + 65536 + t1r * 128 + 4 * tq;
        char* P2 = smc + 65536 + t2r * 128 + 4 * tq;
        const int tsw = t1r & 7;
#pragma unroll
        for (int j = 0; j < 8; j++) {
            const float p0 = __expf(S[j][0] - mn0);
            const float p1 = __expf(S[j][1] - mn0);
            const float p2 = __expf(S[j][2] - mn1);
            const float p3 = __expf(S[j][3] - mn1);
            rs0 += p0 + p1; rs1 += p2 + p3;
            *reinterpret_cast<uint32_t*>(P1 + ((j ^ tsw) << 4)) = packbf(p0, p1);
            *reinterpret_cast<uint32_t*>(P2 + ((j ^ tsw) << 4)) = packbf(p2, p3);
        }
        rs0 = qsum(rs0); rs1 = qsum(rs1);
        l0 = l0 * al0 + rs0;
        l1 = l1 * al1 + rs1;
#pragma unroll
        for (int j = 0; j < 8; j++) {
            O[j][0] *= al0; O[j][1] *= al0;
            O[j][2] *= al1; O[j][3] *= al1;
        }
        __syncwarp();

        const uint32_t pb = sb + 65536;
#pragma unroll
        for (int kk = 0; kk < 4; kk++) {
            uint32_t af[4];
            ldsm4(af, pb + arow * 128 + (((kk * 2 + aoff) ^ (arow & 7)) << 4));
            uint32_t bfr[8][2];
#pragma unroll
            for (int dt = 0; dt < 4; dt++) {
                const int row = dt * 16 + vrow;
                uint32_t r[4];
                ldsm4(r, kbV + row * 128 + (((kk * 2 + voff) ^ (row & 7)) << 4));
                bfr[dt * 2][0] = r[0];     bfr[dt * 2][1] = r[1];
                bfr[dt * 2 + 1][0] = r[2]; bfr[dt * 2 + 1][1] = r[3];
            }
#pragma unroll
            for (int j = 0; j < 8; j++) mma_bf16(O[j], af, bfr[j]);
        }
    }

    const float i0 = 1.f / l0, i1 = 1.f / l1;
    __nv_bfloat16* ab = outaT + ((size_t)b * NL + t0 + tb) * NC + h * 64;
#pragma unroll
    for (int j = 0; j < 8; j++) {
        *reinterpret_cast<uint32_t*>(ab + (size_t)g * NC + j * 8 + tq * 2) =
            packbf(O[j][0] * i0, O[j][1] * i0);
        *reinterpret_cast<uint32_t*>(ab + (size_t)(g + 8) * NC + j * 8 + tq * 2) =
            packbf(O[j][2] * i1, O[j][3] * i1);
    }
}

// ===========================================================================
extern "C" void kernel_launch(void* const* d_in, const int* in_sizes, int n_in,
                              void* d_out, int out_size)
{
    const float* x      = (const float*)d_in[0];
    const float* ctx    = (const float*)d_in[1];
    const float* norm_w = (const float*)d_in[2];
    const float* norm_b = (const float*)d_in[3];
    const float* q_w    = (const float*)d_in[4];
    const float* q_b    = (const float*)d_in[5];
    const float* kv_w   = (const float*)d_in[6];
    const float* kv_b   = (const float*)d_in[7];
    const float* proj_w = (const float*)d_in[8];
    const float* proj_b = (const float*)d_in[9];
    float* out = (float*)d_out;

    __nv_bfloat16 *xnT, *cn, *qp, *kvp, *aT, *qwb, *kvwb, *pwb;
    cudaGetSymbolAddress((void**)&xnT,  g_xnT);
    cudaGetSymbolAddress((void**)&cn,   g_cn);
    cudaGetSymbolAddress((void**)&qp,   g_q);
    cudaGetSymbolAddress((void**)&kvp,  g_kv);
    cudaGetSymbolAddress((void**)&aT,   g_aT);
    cudaGetSymbolAddress((void**)&qwb,  g_qw);
    cudaGetSymbolAddress((void**)&kvwb, g_kvw);
    cudaGetSymbolAddress((void**)&pwb,  g_pw);

    cudaFuncSetAttribute(attn_bf16,
                         cudaFuncAttributeMaxDynamicSharedMemorySize, ATTN_SMEM);
    cudaFuncSetAttribute(gemm_qkv,
                         cudaFuncAttributeMaxDynamicSharedMemorySize, GEMM_SMEM);
    cudaFuncSetAttribute(gemm_proj,
                         cudaFuncAttributeMaxDynamicSharedMemorySize, GEMM_SMEM);

    // 1) GN(x)->xnT, GN(ctx)->cn, all weights -> bf16 (one launch)
    gn_cvt_kernel<<<2560, 512>>>(x, ctx, norm_w, norm_b,
                                 q_w, kv_w, proj_w,
                                 xnT, cn, qwb, kvwb, pwb);

    // 2) q-GEMM + kv-GEMM fused launch
    gemm_qkv<<<dim3(8, 4, 48), 256, GEMM_SMEM>>>(
        xnT, qwb, cn, kvwb, qp, kvp, q_b, kv_b);

    // 3) attention -> aT[b,l,c] bf16
    attn_bf16<<<dim3(4, NB * 8), 256, ATTN_SMEM>>>(qp, kvp, aT);

    // 4) out = x + proj(aT)
    gemm_proj<<<dim3(4, 4, NB), 256, GEMM_SMEM>>>(
        pwb, aT, out, proj_b, x);
}